// round 9
// baseline (speedup 1.0000x reference)
#include <cuda_runtime.h>
#include <cstdint>

#define Bsz 256
#define Tlen 512
#define Iin 5
#define HH 100
#define G4 400
#define NL 5
#define Oout 3
#define BT (Bsz*Tlen)

typedef unsigned long long ull;

#define FMA2(d, a, b, c) asm("fma.rn.f32x2 %0, %1, %2, %3;" : "=l"(d) : "l"(a), "l"(b), "l"(c))
#define ADDF2(d, a, b)   asm("add.rn.f32x2 %0, %1, %2;" : "=l"(d) : "l"(a), "l"(b))
#define PACK2(d, lo, hi) asm("mov.b64 %0, {%1, %2};" : "=l"(d) : "f"(lo), "f"(hi))
#define UNPACK2(lo, hi, v) asm("mov.b64 {%0, %1}, %2;" : "=f"(lo), "=f"(hi) : "l"(v))

// ---------------------------------------------------------------------------
// Scratch
// ---------------------------------------------------------------------------
__device__ float g_gates[(size_t)BT * G4];
__device__ float g_hA[(size_t)BT * HH];
__device__ float g_hB[(size_t)BT * HH];

__device__ __forceinline__ float sigf(float x) {
    return __fdividef(1.0f, 1.0f + __expf(-x));
}
__device__ __forceinline__ float tanh_(float x) {
    return __fdividef(2.0f, 1.0f + __expf(-2.0f * x)) - 1.0f;
}

// ---------------------------------------------------------------------------
// Kernel 1: layers 1..4 input projection (round-6 proven, bit-exact)
// ---------------------------------------------------------------------------
#define GM 64
#define GNJ 7
#define GN (16*GNJ)
#define KP 102
#define GEMM_SMEM ((GM + GN) * KP * 4)

__global__ __launch_bounds__(256)
void gemm_in(int inSel,
             const float* __restrict__ W,
             const float* __restrict__ bias)
{
    extern __shared__ float sm[];
    float* Xs = sm;
    float* Ws = sm + GM * KP;

    const float* X = inSel ? g_hB : g_hA;
    int tid = threadIdx.x;
    int tx = tid & 15;
    int ty = (tid >> 4) & 15;
    size_t m0 = (size_t)blockIdx.x * GM;
    int n0 = blockIdx.y * GN;

    {
        const float2* Xg = (const float2*)(X + m0 * 100);
        for (int idx = tid; idx < GM * 50; idx += 256) {
            int r = idx / 50, c = idx - r * 50;
            float2 v = Xg[(size_t)r * 50 + c];
            *(float2*)&Xs[r * KP + 2 * c] = v;
        }
        const float2* Wg = (const float2*)W;
        for (int idx = tid; idx < GN * 50; idx += 256) {
            int r = idx / 50, c = idx - r * 50;
            int gn = n0 + r;
            float2 v = (gn < G4) ? Wg[(size_t)gn * 50 + c] : make_float2(0.f, 0.f);
            *(float2*)&Ws[r * KP + 2 * c] = v;
        }
    }
    __syncthreads();

    ull acc[4][GNJ];
#pragma unroll
    for (int i = 0; i < 4; i++)
#pragma unroll
        for (int j = 0; j < GNJ; j++) PACK2(acc[i][j], 0.f, 0.f);

    const ull* xrow[4];
#pragma unroll
    for (int i = 0; i < 4; i++) xrow[i] = (const ull*)&Xs[(ty + 16 * i) * KP];
    const ull* wrow[GNJ];
#pragma unroll
    for (int j = 0; j < GNJ; j++) wrow[j] = (const ull*)&Ws[(tx + 16 * j) * KP];

#pragma unroll 5
    for (int k = 0; k < 50; k++) {
        ull dx[4], dw[GNJ];
#pragma unroll
        for (int i = 0; i < 4; i++) dx[i] = xrow[i][k];
#pragma unroll
        for (int j = 0; j < GNJ; j++) dw[j] = wrow[j][k];
#pragma unroll
        for (int i = 0; i < 4; i++)
#pragma unroll
            for (int j = 0; j < GNJ; j++)
                FMA2(acc[i][j], dx[i], dw[j], acc[i][j]);
    }

#pragma unroll
    for (int i = 0; i < 4; i++) {
        size_t m = m0 + ty + 16 * i;
#pragma unroll
        for (int j = 0; j < GNJ; j++) {
            int n = n0 + tx + 16 * j;
            if (n < G4) {
                float lo, hi;
                UNPACK2(lo, hi, acc[i][j]);
                g_gates[m * G4 + n] = lo + hi + bias[n];
            }
        }
    }
}

// ---------------------------------------------------------------------------
// Kernel 2: LSTM recurrence, split-K quad-gate (round-8 structure).
// Template IS_L0: layer 0 computes its own input projection from x (K=5,
// L2-resident) in the prefetch slot -> gemm_in0 + layer-0 g_gates eliminated.
// Gate/x prefetch stays at the validated post-dot position, now predicated
// to half==0 lanes only (half==1 copies were dead).
// ---------------------------------------------------------------------------
template <int IS_L0>
__global__ __launch_bounds__(800, 1)
void lstm_rec(const float* __restrict__ W_hh,   // [400,100]
              int outSel, int storeAll,
              const float* __restrict__ xin,    // [256,512,5] (IS_L0)
              const float* __restrict__ Wih0,   // [400,5]     (IS_L0)
              const float* __restrict__ b0)     // [400]       (IS_L0)
{
    __shared__ __align__(16) float hbuf[2][2][104];  // [parity][row][unit(+pad)]

    const int tid  = threadIdx.x;
    const int u    = tid >> 3;
    const int s    = (tid >> 1) & 3;    // 0=i 1=f 2=g 3=o
    const int half = tid & 1;
    const int grow = s * 100 + u;
    const int b0i  = blockIdx.x * 2;
    const int lane = tid & 31;
    const int lb   = lane & ~7;
    const int cbase = 13 * half;

    // half of the weight row -> 26 packed regs (chunk 25 = zeros)
    ull w2[26];
    {
        const float4* wr = (const float4*)(W_hh + (size_t)grow * HH);
#pragma unroll
        for (int i = 0; i < 13; i++) {
            int cc = cbase + i;
            float4 v = (cc < 25) ? wr[cc] : make_float4(0.f, 0.f, 0.f, 0.f);
            PACK2(w2[2 * i],     v.x, v.y);
            PACK2(w2[2 * i + 1], v.z, v.w);
        }
    }

    // layer-0 input weights + bias (half0 lanes)
    float w0[5] = {0, 0, 0, 0, 0};
    float bg = 0.f;
    if (IS_L0 && half == 0) {
        bg = b0[grow];
#pragma unroll
        for (int k = 0; k < 5; k++) w0[k] = Wih0[grow * 5 + k];
    }

    if (tid < 416) ((float*)hbuf)[tid] = 0.f;
    float c = 0.f;                       // live in lanes (tid&7)<2; row = half

    const float* gp0 = g_gates + (size_t)b0i * Tlen * G4;
    const float* gp1 = gp0 + (size_t)Tlen * G4;
    const float* xr0 = xin ? (xin + (size_t)b0i * Tlen * Iin) : (const float*)0;
    const float* xr1 = xin ? (xr0 + (size_t)Tlen * Iin) : (const float*)0;
    float* hout = outSel ? g_hB : g_hA;
    float* hsrow = hout + (size_t)(b0i + half) * Tlen * HH;  // this lane's row

    float pg0 = 0.f, pg1 = 0.f;
    if (half == 0) {
        if (IS_L0) {
            float a0 = bg, a1 = bg;
#pragma unroll
            for (int k = 0; k < 5; k++) {
                a0 += w0[k] * xr0[k];
                a1 += w0[k] * xr1[k];
            }
            pg0 = a0; pg1 = a1;
        } else {
            pg0 = gp0[grow];
            pg1 = gp1[grow];
        }
    }
    __syncthreads();

    for (int t = 0; t < Tlen; t++) {
        const int p = t & 1;
        const float cur0 = (half == 0) ? pg0 : 0.f;   // preact added once/pair
        const float cur1 = (half == 0) ? pg1 : 0.f;

        // dual-row half-dot
        ull a0, a1, e0, e1;
        PACK2(a0, cur0, 0.f); PACK2(a1, 0.f, 0.f);
        PACK2(e0, cur1, 0.f); PACK2(e1, 0.f, 0.f);
        {
            const ulonglong2* hA = (const ulonglong2*)hbuf[p][0];
            const ulonglong2* hB = (const ulonglong2*)hbuf[p][1];
#pragma unroll
            for (int i = 0; i < 13; i++) {
                ulonglong2 vA = hA[cbase + i];
                ulonglong2 vB = hB[cbase + i];
                FMA2(a0, w2[2 * i],     vA.x, a0);
                FMA2(a1, w2[2 * i + 1], vA.y, a1);
                FMA2(e0, w2[2 * i],     vB.x, e0);
                FMA2(e1, w2[2 * i + 1], vB.y, e1);
            }
        }
        // prefetch next step's pre-activations (validated position: post-dot;
        // predicated to the lanes that consume them)
        if (half == 0) {
            int tn = (t + 1 < Tlen) ? (t + 1) : t;
            if (IS_L0) {
                const float* x0 = xr0 + (size_t)tn * Iin;
                const float* x1 = xr1 + (size_t)tn * Iin;
                float s0 = bg, s1 = bg;
#pragma unroll
                for (int k = 0; k < 5; k++) {
                    s0 += w0[k] * x0[k];
                    s1 += w0[k] * x1[k];
                }
                pg0 = s0; pg1 = s1;
            } else {
                size_t off = (size_t)tn * G4 + grow;
                pg0 = gp0[off];
                pg1 = gp1[off];
            }
        }
        ADDF2(a0, a0, a1);
        ADDF2(e0, e0, e1);
        float q0, q1;
        UNPACK2(q0, q1, a0); float part0 = q0 + q1;
        UNPACK2(q0, q1, e0); float part1 = q0 + q1;

        // combine K halves
        float full0 = part0 + __shfl_xor_sync(0xFFFFFFFFu, part0, 1);
        float full1 = part1 + __shfl_xor_sync(0xFFFFFFFFu, part1, 1);

        // activate ONLY this lane's row (row = half)
        float myfull = half ? full1 : full0;
        float v = (s == 2) ? tanh_(myfull) : sigf(myfull);

        // gather f,g,o for my row (source lanes lb+2/4/6, +half selects row)
        float fv = __shfl_sync(0xFFFFFFFFu, v, lb + 2 + half);
        float gv = __shfl_sync(0xFFFFFFFFu, v, lb + 4 + half);
        float ov = __shfl_sync(0xFFFFFFFFu, v, lb + 6 + half);

        // state update: lane lb -> row0, lane lb+1 -> row1
        const int pn = p ^ 1;
        if ((tid & 7) < 2) {             // s==0; v = my row's input gate
            c = fv * c + v * gv;
            float h = ov * tanh_(c);
            hbuf[pn][half][u] = h;
            if (storeAll || t == Tlen - 1) hsrow[(size_t)t * HH + u] = h;
        }
        __syncthreads();
    }
}

// ---------------------------------------------------------------------------
// Kernel 3: BN + MLP head
// ---------------------------------------------------------------------------
__global__ void head_kernel(int inSel,
                            const float* __restrict__ gamma,
                            const float* __restrict__ beta,
                            const float* __restrict__ rmean,
                            const float* __restrict__ rvar,
                            const float* __restrict__ W1, const float* __restrict__ b1,
                            const float* __restrict__ W2, const float* __restrict__ b2,
                            const float* __restrict__ W3, const float* __restrict__ b3,
                            float* __restrict__ out)
{
    __shared__ float xa[HH], ya[HH];
    const float* hseq = inSel ? g_hB : g_hA;
    int b = blockIdx.x, tid = threadIdx.x;

    if (tid < HH) {
        float v = hseq[((size_t)b * Tlen + (Tlen - 1)) * HH + tid];
        xa[tid] = (v - rmean[tid]) * rsqrtf(rvar[tid] + 1e-5f) * gamma[tid] + beta[tid];
    }
    __syncthreads();
    if (tid < HH) {
        float a = b1[tid];
#pragma unroll 4
        for (int k = 0; k < HH; k++) a += xa[k] * W1[(size_t)tid * HH + k];
        ya[tid] = fmaxf(a, 0.0f);
    }
    __syncthreads();
    if (tid < HH) {
        float a = b2[tid];
#pragma unroll 4
        for (int k = 0; k < HH; k++) a += ya[k] * W2[(size_t)tid * HH + k];
        xa[tid] = fmaxf(a, 0.0f);
    }
    __syncthreads();
    if (tid < Oout) {
        float a = b3[tid];
#pragma unroll 4
        for (int k = 0; k < HH; k++) a += xa[k] * W3[(size_t)tid * HH + k];
        out[(size_t)b * Oout + tid] = a;
    }
}

// ---------------------------------------------------------------------------
// kernel_launch
// ---------------------------------------------------------------------------
extern "C" void kernel_launch(void* const* d_in, const int* in_sizes, int n_in,
                              void* d_out, int out_size)
{
    const float* x     = (const float*)d_in[0];
    const float* W_ih0 = (const float*)d_in[1];
    const float* W_hh0 = (const float*)d_in[2];
    const float* b0    = (const float*)d_in[3];
    const float* W_ih  = (const float*)d_in[4];
    const float* W_hh  = (const float*)d_in[5];
    const float* bb    = (const float*)d_in[6];
    const float* gamma = (const float*)d_in[7];
    const float* beta  = (const float*)d_in[8];
    const float* rmean = (const float*)d_in[9];
    const float* rvar  = (const float*)d_in[10];
    const float* W1    = (const float*)d_in[11];
    const float* b1    = (const float*)d_in[12];
    const float* W2    = (const float*)d_in[13];
    const float* b2    = (const float*)d_in[14];
    const float* W3    = (const float*)d_in[15];
    const float* b3    = (const float*)d_in[16];
    float* out = (float*)d_out;

    static int smem_set = 0;
    if (!smem_set) {
        cudaFuncSetAttribute((const void*)gemm_in,
                             cudaFuncAttributeMaxDynamicSharedMemorySize, GEMM_SMEM);
        smem_set = 1;
    }

    // Layer 0: fused input projection (x is L2-resident) + recurrence -> g_hA
    lstm_rec<1><<<128, 800>>>(W_hh0, 0, 1, x, W_ih0, b0);

    // Layers 1..4
    dim3 ggrid(BT / GM, 4);
    for (int l = 0; l < NL - 1; l++) {
        int inSel  = (l % 2 == 0) ? 0 : 1;
        int outSel = 1 - inSel;
        gemm_in<<<ggrid, 256, GEMM_SMEM>>>(inSel, W_ih + (size_t)l * G4 * HH,
                                           bb + (size_t)l * G4);
        lstm_rec<0><<<128, 800>>>(W_hh + (size_t)l * G4 * HH, outSel,
                                  (l == NL - 2) ? 0 : 1,
                                  (const float*)0, (const float*)0, (const float*)0);
    }

    head_kernel<<<Bsz, 128>>>(0, gamma, beta, rmean, rvar,
                              W1, b1, W2, b2, W3, b3, out);
}

// round 10
// speedup vs baseline: 1.3893x; 1.3893x over previous
#include <cuda_runtime.h>
#include <cstdint>

#define Bsz 256
#define Tlen 512
#define Iin 5
#define HH 100
#define G4 400
#define NL 5
#define Oout 3
#define BT (Bsz*Tlen)

typedef unsigned long long ull;

#define FMA2(d, a, b, c) asm("fma.rn.f32x2 %0, %1, %2, %3;" : "=l"(d) : "l"(a), "l"(b), "l"(c))
#define ADDF2(d, a, b)   asm("add.rn.f32x2 %0, %1, %2;" : "=l"(d) : "l"(a), "l"(b))
#define PACK2(d, lo, hi) asm("mov.b64 %0, {%1, %2};" : "=l"(d) : "f"(lo), "f"(hi))
#define UNPACK2(lo, hi, v) asm("mov.b64 {%0, %1}, %2;" : "=f"(lo), "=f"(hi) : "l"(v))

// ---------------------------------------------------------------------------
// Scratch
// ---------------------------------------------------------------------------
__device__ float g_gates[(size_t)BT * G4];
__device__ float g_hA[(size_t)BT * HH];
__device__ float g_hB[(size_t)BT * HH];

__device__ __forceinline__ float sigf(float x) {
    return __fdividef(1.0f, 1.0f + __expf(-x));
}
__device__ __forceinline__ float tanh_(float x) {
    return __fdividef(2.0f, 1.0f + __expf(-2.0f * x)) - 1.0f;
}

// ---------------------------------------------------------------------------
// Kernel 1a: layer-0 input projection (K=5) — round-6 exact
// ---------------------------------------------------------------------------
__global__ void gemm_in0(const float* __restrict__ x,
                         const float* __restrict__ Wih,
                         const float* __restrict__ bias)
{
    int idx = blockIdx.x * blockDim.x + threadIdx.x;
    int m = idx / G4;
    int n = idx - m * G4;
    const float* xr = x + (size_t)m * Iin;
    const float* wr = Wih + (size_t)n * Iin;
    float a = bias[n];
#pragma unroll
    for (int k = 0; k < Iin; k++) a += xr[k] * wr[k];
    g_gates[(size_t)idx] = a;
}

// ---------------------------------------------------------------------------
// Kernel 1b: layers 1..4 input projection — round-6 exact (verified 344us)
// ---------------------------------------------------------------------------
#define GM 64
#define GNJ 7
#define GN (16*GNJ)
#define KP 102
#define GEMM_SMEM ((GM + GN) * KP * 4)

__global__ __launch_bounds__(256)
void gemm_in(int inSel,
             const float* __restrict__ W,
             const float* __restrict__ bias)
{
    extern __shared__ float sm[];
    float* Xs = sm;
    float* Ws = sm + GM * KP;

    const float* X = inSel ? g_hB : g_hA;
    int tid = threadIdx.x;
    int tx = tid & 15;
    int ty = (tid >> 4) & 15;
    size_t m0 = (size_t)blockIdx.x * GM;
    int n0 = blockIdx.y * GN;

    {
        const float2* Xg = (const float2*)(X + m0 * 100);
        for (int idx = tid; idx < GM * 50; idx += 256) {
            int r = idx / 50, c = idx - r * 50;
            float2 v = Xg[(size_t)r * 50 + c];
            *(float2*)&Xs[r * KP + 2 * c] = v;
        }
        const float2* Wg = (const float2*)W;
        for (int idx = tid; idx < GN * 50; idx += 256) {
            int r = idx / 50, c = idx - r * 50;
            int gn = n0 + r;
            float2 v = (gn < G4) ? Wg[(size_t)gn * 50 + c] : make_float2(0.f, 0.f);
            *(float2*)&Ws[r * KP + 2 * c] = v;
        }
    }
    __syncthreads();

    ull acc[4][GNJ];
#pragma unroll
    for (int i = 0; i < 4; i++)
#pragma unroll
        for (int j = 0; j < GNJ; j++) PACK2(acc[i][j], 0.f, 0.f);

    const ull* xrow[4];
#pragma unroll
    for (int i = 0; i < 4; i++) xrow[i] = (const ull*)&Xs[(ty + 16 * i) * KP];
    const ull* wrow[GNJ];
#pragma unroll
    for (int j = 0; j < GNJ; j++) wrow[j] = (const ull*)&Ws[(tx + 16 * j) * KP];

#pragma unroll 5
    for (int k = 0; k < 50; k++) {
        ull dx[4], dw[GNJ];
#pragma unroll
        for (int i = 0; i < 4; i++) dx[i] = xrow[i][k];
#pragma unroll
        for (int j = 0; j < GNJ; j++) dw[j] = wrow[j][k];
#pragma unroll
        for (int i = 0; i < 4; i++)
#pragma unroll
            for (int j = 0; j < GNJ; j++)
                FMA2(acc[i][j], dx[i], dw[j], acc[i][j]);
    }

#pragma unroll
    for (int i = 0; i < 4; i++) {
        size_t m = m0 + ty + 16 * i;
#pragma unroll
        for (int j = 0; j < GNJ; j++) {
            int n = n0 + tx + 16 * j;
            if (n < G4) {
                float lo, hi;
                UNPACK2(lo, hi, acc[i][j]);
                g_gates[m * G4 + n] = lo + hi + bias[n];
            }
        }
    }
}

// ---------------------------------------------------------------------------
// Kernel 2: LSTM recurrence — round-8 exact (verified 597us/layer)
// ---------------------------------------------------------------------------
__global__ __launch_bounds__(800, 1)
void lstm_rec(const float* __restrict__ W_hh,   // [400,100]
              int outSel, int storeAll)
{
    __shared__ __align__(16) float hbuf[2][2][104];  // [parity][row][unit(+pad)]

    const int tid  = threadIdx.x;
    const int u    = tid >> 3;
    const int s    = (tid >> 1) & 3;    // 0=i 1=f 2=g 3=o
    const int half = tid & 1;
    const int grow = s * 100 + u;
    const int b0   = blockIdx.x * 2;
    const int lane = tid & 31;
    const int lb   = lane & ~7;
    const int cbase = 13 * half;

    // half of the weight row -> 26 packed regs (chunk 25 = zeros)
    ull w2[26];
    {
        const float4* wr = (const float4*)(W_hh + (size_t)grow * HH);
#pragma unroll
        for (int i = 0; i < 13; i++) {
            int cc = cbase + i;
            float4 v = (cc < 25) ? wr[cc] : make_float4(0.f, 0.f, 0.f, 0.f);
            PACK2(w2[2 * i],     v.x, v.y);
            PACK2(w2[2 * i + 1], v.z, v.w);
        }
    }

    if (tid < 416) ((float*)hbuf)[tid] = 0.f;
    float c = 0.f;                       // live in lanes (tid&7)<2; row = half

    const float* gp0 = g_gates + (size_t)b0 * Tlen * G4;
    const float* gp1 = gp0 + (size_t)Tlen * G4;
    float* hout = outSel ? g_hB : g_hA;
    float* hsrow = hout + (size_t)(b0 + half) * Tlen * HH;   // this lane's row

    float pg0 = gp0[grow];
    float pg1 = gp1[grow];
    __syncthreads();

    for (int t = 0; t < Tlen; t++) {
        const int p = t & 1;
        const float cur0 = (half == 0) ? pg0 : 0.f;   // preact added once/pair
        const float cur1 = (half == 0) ? pg1 : 0.f;

        // dual-row half-dot
        ull a0, a1, e0, e1;
        PACK2(a0, cur0, 0.f); PACK2(a1, 0.f, 0.f);
        PACK2(e0, cur1, 0.f); PACK2(e1, 0.f, 0.f);
        {
            const ulonglong2* hA = (const ulonglong2*)hbuf[p][0];
            const ulonglong2* hB = (const ulonglong2*)hbuf[p][1];
#pragma unroll
            for (int i = 0; i < 13; i++) {
                ulonglong2 vA = hA[cbase + i];
                ulonglong2 vB = hB[cbase + i];
                FMA2(a0, w2[2 * i],     vA.x, a0);
                FMA2(a1, w2[2 * i + 1], vA.y, a1);
                FMA2(e0, w2[2 * i],     vB.x, e0);
                FMA2(e1, w2[2 * i + 1], vB.y, e1);
            }
        }
        // prefetch next step's pre-activations (round-6/8 position: after dot,
        // ALL lanes, unpredicated — verified fastest placement)
        {
            int tn = (t + 1 < Tlen) ? (t + 1) : t;
            pg0 = gp0[(size_t)tn * G4 + grow];
            pg1 = gp1[(size_t)tn * G4 + grow];
        }
        ADDF2(a0, a0, a1);
        ADDF2(e0, e0, e1);
        float q0, q1;
        UNPACK2(q0, q1, a0); float part0 = q0 + q1;
        UNPACK2(q0, q1, e0); float part1 = q0 + q1;

        // combine K halves
        float full0 = part0 + __shfl_xor_sync(0xFFFFFFFFu, part0, 1);
        float full1 = part1 + __shfl_xor_sync(0xFFFFFFFFu, part1, 1);

        // activate ONLY this lane's row (row = half)
        float myfull = half ? full1 : full0;
        float v = (s == 2) ? tanh_(myfull) : sigf(myfull);

        // gather f,g,o for my row (source lanes lb+2/4/6, +half selects row)
        float fv = __shfl_sync(0xFFFFFFFFu, v, lb + 2 + half);
        float gv = __shfl_sync(0xFFFFFFFFu, v, lb + 4 + half);
        float ov = __shfl_sync(0xFFFFFFFFu, v, lb + 6 + half);

        // state update: lane lb -> row0, lane lb+1 -> row1
        const int pn = p ^ 1;
        if ((tid & 7) < 2) {             // s==0; v = my row's input gate
            c = fv * c + v * gv;
            float h = ov * tanh_(c);
            hbuf[pn][half][u] = h;
            if (storeAll || t == Tlen - 1) hsrow[(size_t)t * HH + u] = h;
        }
        __syncthreads();
    }
}

// ---------------------------------------------------------------------------
// Kernel 3: BN + MLP head
// ---------------------------------------------------------------------------
__global__ void head_kernel(int inSel,
                            const float* __restrict__ gamma,
                            const float* __restrict__ beta,
                            const float* __restrict__ rmean,
                            const float* __restrict__ rvar,
                            const float* __restrict__ W1, const float* __restrict__ b1,
                            const float* __restrict__ W2, const float* __restrict__ b2,
                            const float* __restrict__ W3, const float* __restrict__ b3,
                            float* __restrict__ out)
{
    __shared__ float xa[HH], ya[HH];
    const float* hseq = inSel ? g_hB : g_hA;
    int b = blockIdx.x, tid = threadIdx.x;

    if (tid < HH) {
        float v = hseq[((size_t)b * Tlen + (Tlen - 1)) * HH + tid];
        xa[tid] = (v - rmean[tid]) * rsqrtf(rvar[tid] + 1e-5f) * gamma[tid] + beta[tid];
    }
    __syncthreads();
    if (tid < HH) {
        float a = b1[tid];
#pragma unroll 4
        for (int k = 0; k < HH; k++) a += xa[k] * W1[(size_t)tid * HH + k];
        ya[tid] = fmaxf(a, 0.0f);
    }
    __syncthreads();
    if (tid < HH) {
        float a = b2[tid];
#pragma unroll 4
        for (int k = 0; k < HH; k++) a += ya[k] * W2[(size_t)tid * HH + k];
        xa[tid] = fmaxf(a, 0.0f);
    }
    __syncthreads();
    if (tid < Oout) {
        float a = b3[tid];
#pragma unroll 4
        for (int k = 0; k < HH; k++) a += xa[k] * W3[(size_t)tid * HH + k];
        out[(size_t)b * Oout + tid] = a;
    }
}

// ---------------------------------------------------------------------------
// kernel_launch
// ---------------------------------------------------------------------------
extern "C" void kernel_launch(void* const* d_in, const int* in_sizes, int n_in,
                              void* d_out, int out_size)
{
    const float* x     = (const float*)d_in[0];
    const float* W_ih0 = (const float*)d_in[1];
    const float* W_hh0 = (const float*)d_in[2];
    const float* b0    = (const float*)d_in[3];
    const float* W_ih  = (const float*)d_in[4];
    const float* W_hh  = (const float*)d_in[5];
    const float* bb    = (const float*)d_in[6];
    const float* gamma = (const float*)d_in[7];
    const float* beta  = (const float*)d_in[8];
    const float* rmean = (const float*)d_in[9];
    const float* rvar  = (const float*)d_in[10];
    const float* W1    = (const float*)d_in[11];
    const float* b1    = (const float*)d_in[12];
    const float* W2    = (const float*)d_in[13];
    const float* b2    = (const float*)d_in[14];
    const float* W3    = (const float*)d_in[15];
    const float* b3    = (const float*)d_in[16];
    float* out = (float*)d_out;

    static int smem_set = 0;
    if (!smem_set) {
        cudaFuncSetAttribute((const void*)gemm_in,
                             cudaFuncAttributeMaxDynamicSharedMemorySize, GEMM_SMEM);
        smem_set = 1;
    }

    gemm_in0<<<(BT * G4) / 256, 256>>>(x, W_ih0, b0);
    lstm_rec<<<128, 800>>>(W_hh0, 0, 1);

    dim3 ggrid(BT / GM, 4);
    for (int l = 0; l < NL - 1; l++) {
        int inSel  = (l % 2 == 0) ? 0 : 1;
        int outSel = 1 - inSel;
        gemm_in<<<ggrid, 256, GEMM_SMEM>>>(inSel, W_ih + (size_t)l * G4 * HH,
                                           bb + (size_t)l * G4);
        lstm_rec<<<128, 800>>>(W_hh + (size_t)l * G4 * HH, outSel,
                               (l == NL - 2) ? 0 : 1);
    }

    head_kernel<<<Bsz, 128>>>(0, gamma, beta, rmean, rvar,
                              W1, b1, W2, b2, W3, b3, out);
}